// round 9
// baseline (speedup 1.0000x reference)
#include <cuda_runtime.h>
#include <cooperative_groups.h>
#include <math.h>

namespace cg = cooperative_groups;

#define Bq   4
#define Tq   2048
#define INq  64
#define Hq   256
#define Dq   512
#define G4q  1024
#define EPSq 1e-5f

// ---------------- static scratch ----------------
__device__ float g_gx0[Bq * Tq * G4q];
__device__ float g_gx1[Bq * Tq * G4q];
__device__ float g_h1 [Bq * Tq * Hq];
__device__ float g_h2 [Bq * Tq * Hq];
__device__ float g_cv [Bq * Tq * Hq];
__device__ float g_kv [Bq * Tq * G4q];
__device__ float g_at [Bq * Dq];

#define FMA_F32X2(d, a, b, c) \
    asm("fma.rn.f32x2 %0, %1, %2, %3;" : "=l"(d) : "l"(a), "l"(b), "l"(c))

__device__ __forceinline__ float hsum_f32x2(unsigned long long v) {
    float lo, hi;
    asm("mov.b64 {%0, %1}, %2;" : "=f"(lo), "=f"(hi) : "l"(v));
    return lo + hi;
}

// single-MUFU tanh (sm_75+); sigmoid via tanh identity
__device__ __forceinline__ float tanha(float x) {
    float y; asm("tanh.approx.f32 %0, %1;" : "=f"(y) : "f"(x)); return y;
}
__device__ __forceinline__ float sigt(float x) {
    return fmaf(0.5f, tanha(0.5f * x), 0.5f);
}

// ---------------- GEMM 128x64 tiles ----------------
__global__ __launch_bounds__(256) void gemm128(
    const float* __restrict__ A1, const float* __restrict__ A2,
    int Ksplit, int K,
    const float* __restrict__ W, const float* __restrict__ b1,
    const float* __restrict__ b2, float* __restrict__ out, int N)
{
    __shared__ float As[16][128];
    __shared__ float Bs[16][64];
    const int m0 = blockIdx.x * 128, n0 = blockIdx.y * 64;
    const int tid = threadIdx.x;
    const int tx = tid & 15, ty = tid >> 4;
    const int lmA = tid & 127, khA = (tid >> 7) * 8;
    const int lnB = tid & 63,  kB  = (tid >> 6) * 4;
    const int K2 = K - Ksplit;

    float acc[8][4];
#pragma unroll
    for (int i = 0; i < 8; i++)
#pragma unroll
        for (int j = 0; j < 4; j++) acc[i][j] = 0.f;

    for (int k0 = 0; k0 < K; k0 += 16) {
        {
            int m = m0 + lmA;
#pragma unroll
            for (int half = 0; half < 2; half++) {
                int off = khA + half * 4;
                int kg = k0 + off;
                float4 v;
                if (kg < Ksplit) v = *(const float4*)(A1 + (size_t)m * Ksplit + kg);
                else             v = *(const float4*)(A2 + (size_t)m * K2 + (kg - Ksplit));
                As[off + 0][lmA] = v.x; As[off + 1][lmA] = v.y;
                As[off + 2][lmA] = v.z; As[off + 3][lmA] = v.w;
            }
            int n = n0 + lnB;
            float4 wv = *(const float4*)(W + (size_t)n * K + k0 + kB);
            Bs[kB + 0][lnB] = wv.x; Bs[kB + 1][lnB] = wv.y;
            Bs[kB + 2][lnB] = wv.z; Bs[kB + 3][lnB] = wv.w;
        }
        __syncthreads();
#pragma unroll
        for (int kk = 0; kk < 16; kk++) {
            float4 a0 = *(const float4*)&As[kk][ty * 8];
            float4 a1 = *(const float4*)&As[kk][ty * 8 + 4];
            float4 b  = *(const float4*)&Bs[kk][tx * 4];
            float av[8] = {a0.x, a0.y, a0.z, a0.w, a1.x, a1.y, a1.z, a1.w};
#pragma unroll
            for (int i = 0; i < 8; i++) {
                acc[i][0] = fmaf(av[i], b.x, acc[i][0]);
                acc[i][1] = fmaf(av[i], b.y, acc[i][1]);
                acc[i][2] = fmaf(av[i], b.z, acc[i][2]);
                acc[i][3] = fmaf(av[i], b.w, acc[i][3]);
            }
        }
        __syncthreads();
    }

    float bias[4];
#pragma unroll
    for (int j = 0; j < 4; j++) {
        int n = n0 + tx * 4 + j;
        bias[j] = b1[n] + (b2 ? b2[n] : 0.f);
    }
#pragma unroll
    for (int i = 0; i < 8; i++) {
        int m = m0 + ty * 8 + i;
        float4 r = make_float4(acc[i][0] + bias[0], acc[i][1] + bias[1],
                               acc[i][2] + bias[2], acc[i][3] + bias[3]);
        *(float4*)(out + (size_t)m * N + n0 + tx * 4) = r;
    }
}

// ---------------- conv1d(K=5,same) + BN + SiLU ----------------
__global__ __launch_bounds__(256, 1) void conv_bn_silu(
    const float* __restrict__ x, const float* __restrict__ cw,
    const float* __restrict__ cb, const float* __restrict__ bg,
    const float* __restrict__ bnb, const float* __restrict__ bmean,
    const float* __restrict__ bvar)
{
    extern __shared__ float sm[];
    float* xs = sm;              // [36][64]
    float* ws = sm + 36 * 64;    // [64][321]
    const int b = blockIdx.z;
    const int t0 = blockIdx.x * 32;
    const int ocb = blockIdx.y * 64;
    const int tid = threadIdx.x;

    for (int idx = tid; idx < 36 * 64; idx += 256) {
        int tr = idx >> 6, i = idx & 63;
        int tg = t0 + tr - 2;
        xs[idx] = (tg >= 0 && tg < Tq) ? x[((size_t)b * Tq + tg) * INq + i] : 0.f;
    }
    for (int idx = tid; idx < 64 * 320; idx += 256) {
        int o = idx / 320, ik = idx % 320;
        ws[o * 321 + ik] = cw[(size_t)(ocb + o) * 320 + ik];
    }
    __syncthreads();

    const int o = tid & 63, gq = tid >> 6;
    const int tb = gq * 8;
    float acc[8];
#pragma unroll
    for (int t = 0; t < 8; t++) acc[t] = 0.f;

    for (int i = 0; i < 64; i++) {
        float xv[12];
#pragma unroll
        for (int j = 0; j < 12; j++) xv[j] = xs[(tb + j) * 64 + i];
#pragma unroll
        for (int k = 0; k < 5; k++) {
            float wv = ws[o * 321 + i * 5 + k];
#pragma unroll
            for (int t = 0; t < 8; t++) acc[t] = fmaf(xv[t + k], wv, acc[t]);
        }
    }
    const int oc = ocb + o;
    float scl = rsqrtf(bvar[oc] + EPSq) * bg[oc];
    float sh = bnb[oc] - bmean[oc] * scl;
    float cbv = cb[oc];
#pragma unroll
    for (int t = 0; t < 8; t++) {
        float y = (acc[t] + cbv) * scl + sh;
        g_cv[((size_t)b * Tq + t0 + tb + t) * Hq + oc] = y / (1.f + __expf(-y));
    }
}

// ---------------- mbarrier / st.async helpers ----------------
#define MBAR_WAIT_ACQ_CLUSTER(addr, par) do {                                    \
    unsigned _done;                                                              \
    asm volatile("{\n\t.reg .pred P;\n\t"                                        \
        "mbarrier.try_wait.parity.acquire.cluster.shared::cta.b64 P, [%1], %2;\n\t" \
        "selp.b32 %0, 1, 0, P;\n\t}"                                             \
        : "=r"(_done) : "r"(addr), "r"(par) : "memory");                         \
    while (!_done) {                                                             \
        asm volatile("{\n\t.reg .pred P;\n\t"                                    \
            "mbarrier.try_wait.parity.acquire.cluster.shared::cta.b64 P, [%1], %2, 0x989680;\n\t" \
            "selp.b32 %0, 1, 0, P;\n\t}"                                         \
            : "=r"(_done) : "r"(addr), "r"(par) : "memory");                     \
    }                                                                            \
} while (0)

#define MBAR_ARM(addr, bytes) \
    asm volatile("mbarrier.arrive.expect_tx.shared.b64 _, [%0], %1;"             \
                 :: "r"(addr), "r"(bytes) : "memory")

#define ST_ASYNC_V4(daddr, r0, r1, r2, r3, mbaraddr) \
    asm volatile("st.async.weak.shared::cluster.mbarrier::complete_tx::bytes.v4.b32 " \
                 "[%0], {%1, %2, %3, %4}, [%5];"                                 \
                 :: "r"(daddr), "r"(r0), "r"(r1), "r"(r2), "r"(r3),              \
                    "r"(mbaraddr) : "memory")

__device__ __forceinline__ uint32_t smem_u32(const void* p) {
    uint32_t a;
    asm("{ .reg .u64 t; cvta.to.shared.u64 t, %1; cvt.u32.u64 %0, t; }"
        : "=r"(a) : "l"(p));
    return a;
}
__device__ __forceinline__ uint32_t mapa_u32(uint32_t a, int r) {
    uint32_t o;
    asm("mapa.shared::cluster.u32 %0, %1, %2;" : "=r"(o) : "r"(a), "r"(r));
    return o;
}

// ---------------- LSTM scan: 2 clusters x 8 CTAs, TWO batches per cluster -----
// Same register-resident packed weights serve both batches. Per step the two
// independent recurrences interleave, overlapping each other's st.async flight
// and mbar-wait latency. Per-batch double-buffered h + per-batch mbar pairs.
// Senders: lanes 0-15; lane = batchSel*8 + destCTA; one st.async.v4 each.
__global__ void __cluster_dims__(8, 1, 1) __launch_bounds__(256, 1) lstm_scan(
    const float* __restrict__ gx, const float* __restrict__ w_hh,
    float* __restrict__ h_out)
{
    __shared__ alignas(16) float h2s[2][2][256];   // [batch][parity][unit]
    __shared__ alignas(16) unsigned long long mbars[4]; // [batch*2 + parity]

    cg::cluster_group cluster = cg::this_cluster();
    const int rank  = (int)cluster.block_rank();
    const int batchA = (blockIdx.x >> 3) * 2;      // cluster c -> batches 2c, 2c+1
    const int tid = threadIdx.x;
    const int w = tid >> 5, l = tid & 31;
    const int v  = l & 3;
    const int g  = (l >> 2) & 3;
    const int kh = l >> 4;
    const int gunit = rank * 32 + w * 4 + v;     // global hidden unit 0..255
    const int row = g * Hq + gunit;              // gate row 0..1023

    // this thread's 128 weights, packed as 64 x f32x2 (pairs along k)
    unsigned long long wreg[64];
    {
        const ulonglong2* wp = (const ulonglong2*)(w_hh + (size_t)row * Hq + (kh << 7));
#pragma unroll
        for (int i = 0; i < 32; i++) {
            ulonglong2 t2 = wp[i];
            wreg[2 * i]     = t2.x;
            wreg[2 * i + 1] = t2.y;
        }
    }

    for (int i = tid; i < 1024; i += 256) ((float*)h2s)[i] = 0.f;

    const uint32_t mbb = smem_u32(&mbars[0]);   // mbars[i] at mbb + 8*i
    if (tid == 0) {
#pragma unroll
        for (int i = 0; i < 4; i++)
            asm volatile("mbarrier.init.shared.b64 [%0], 1;"
                         :: "r"(mbb + 8u * i) : "memory");
        // arm both batches: parity-1 mbar for step 1, parity-0 mbar for step 2
        MBAR_ARM(mbb + 8u * 1, 1024);  // A, parity slot 1
        MBAR_ARM(mbb + 8u * 0, 1024);  // A, parity slot 0
        MBAR_ARM(mbb + 8u * 3, 1024);  // B, parity slot 1
        MBAR_ARM(mbb + 8u * 2, 1024);  // B, parity slot 0
    }

    // sender lanes 0..15: batchSel = l>>3, dest = l&7
    const uint32_t h0_local = smem_u32(&h2s[0][0][0]);
    const int dest = l & 7;
    const int bsel = (l >> 3) & 1;
    uint32_t peer_h[2], peer_mb[2];   // [parity] for this lane's (batch,dest)
    {
        uint32_t base = mapa_u32(h0_local, dest);
        uint32_t blk = (uint32_t)((rank * 32 + w * 4) * 4);   // 16B-aligned
        peer_h[0] = base + (uint32_t)(bsel * 2048) + blk;
        peer_h[1] = base + (uint32_t)(bsel * 2048) + 1024u + blk;
        peer_mb[0] = mapa_u32(mbb + 8u * (bsel * 2 + 0), dest);
        peer_mb[1] = mapa_u32(mbb + 8u * (bsel * 2 + 1), dest);
    }

    cluster.sync();

    const float* gxA = gx + (size_t)batchA * Tq * G4q + row;
    const float* gxB = gx + (size_t)(batchA + 1) * Tq * G4q + row;
    const bool write_out = ((l >> 2) == rank);   // 4 lanes/warp write h_out
    const bool sender = (l < 16);
    float cA = 0.f, cB = 0.f;
    float curA = gxA[0], curB = gxB[0];

    for (int t = 0; t < Tq; t++) {
        // prefetch next-step gx for both batches before any waiting
        float nxtA = 0.f, nxtB = 0.f;
        if (t + 1 < Tq) {
            nxtA = gxA[(size_t)(t + 1) * G4q];
            nxtB = gxB[(size_t)(t + 1) * G4q];
        }
        const int p = t & 1;
        const unsigned par = (unsigned)(((t >> 1) + (p ^ 1)) & 1);
        const int q = p ^ 1;   // parity slot for the h(t+1) we will send

        // ---------------- batch A ----------------
        {
            if (t > 0) {
                const uint32_t mb = mbb + 8u * (unsigned)p;
                MBAR_WAIT_ACQ_CLUSTER(mb, par);
                if (tid == 0 && t + 2 < Tq) MBAR_ARM(mb, 1024);
            }
            const ulonglong2* hb2 = (const ulonglong2*)&h2s[0][p][kh << 7];
            unsigned long long a0 = 0ull, a1 = 0ull, a2 = 0ull, a3 = 0ull;
#pragma unroll
            for (int i = 0; i < 32; i += 2) {
                ulonglong2 hv0 = hb2[i];
                ulonglong2 hv1 = hb2[i + 1];
                FMA_F32X2(a0, wreg[2 * i + 0], hv0.x, a0);
                FMA_F32X2(a1, wreg[2 * i + 1], hv0.y, a1);
                FMA_F32X2(a2, wreg[2 * i + 2], hv1.x, a2);
                FMA_F32X2(a3, wreg[2 * i + 3], hv1.y, a3);
            }
            float partial = (hsum_f32x2(a0) + hsum_f32x2(a1))
                          + (hsum_f32x2(a2) + hsum_f32x2(a3));
            float sum = partial + __shfl_xor_sync(0xFFFFFFFFu, partial, 16);
            sum += curA;
            float si = __shfl_sync(0xFFFFFFFFu, sum, v);
            float sf = __shfl_sync(0xFFFFFFFFu, sum, v + 4);
            float sg = __shfl_sync(0xFFFFFFFFu, sum, v + 8);
            float so = __shfl_sync(0xFFFFFFFFu, sum, v + 12);
            cA = sigt(sf) * cA + sigt(si) * tanha(sg);
            float hnew = sigt(so) * tanha(cA);
            if (write_out)
                h_out[((size_t)batchA * Tq + t) * Hq + gunit] = hnew;
            if (t + 1 < Tq) {
                unsigned hu = __float_as_uint(hnew);
                unsigned f0 = __shfl_sync(0xFFFFFFFFu, hu, 0);
                unsigned f1 = __shfl_sync(0xFFFFFFFFu, hu, 1);
                unsigned f2 = __shfl_sync(0xFFFFFFFFu, hu, 2);
                unsigned f3 = __shfl_sync(0xFFFFFFFFu, hu, 3);
                if (sender && bsel == 0)
                    ST_ASYNC_V4(peer_h[q], f0, f1, f2, f3, peer_mb[q]);
            }
            curA = nxtA;
        }

        // ---------------- batch B ----------------
        {
            if (t > 0) {
                const uint32_t mb = mbb + 8u * (unsigned)(2 + p);
                MBAR_WAIT_ACQ_CLUSTER(mb, par);
                if (tid == 0 && t + 2 < Tq) MBAR_ARM(mb, 1024);
            }
            const ulonglong2* hb2 = (const ulonglong2*)&h2s[1][p][kh << 7];
            unsigned long long a0 = 0ull, a1 = 0ull, a2 = 0ull, a3 = 0ull;
#pragma unroll
            for (int i = 0; i < 32; i += 2) {
                ulonglong2 hv0 = hb2[i];
                ulonglong2 hv1 = hb2[i + 1];
                FMA_F32X2(a0, wreg[2 * i + 0], hv0.x, a0);
                FMA_F32X2(a1, wreg[2 * i + 1], hv0.y, a1);
                FMA_F32X2(a2, wreg[2 * i + 2], hv1.x, a2);
                FMA_F32X2(a3, wreg[2 * i + 3], hv1.y, a3);
            }
            float partial = (hsum_f32x2(a0) + hsum_f32x2(a1))
                          + (hsum_f32x2(a2) + hsum_f32x2(a3));
            float sum = partial + __shfl_xor_sync(0xFFFFFFFFu, partial, 16);
            sum += curB;
            float si = __shfl_sync(0xFFFFFFFFu, sum, v);
            float sf = __shfl_sync(0xFFFFFFFFu, sum, v + 4);
            float sg = __shfl_sync(0xFFFFFFFFu, sum, v + 8);
            float so = __shfl_sync(0xFFFFFFFFu, sum, v + 12);
            cB = sigt(sf) * cB + sigt(si) * tanha(sg);
            float hnew = sigt(so) * tanha(cB);
            if (write_out)
                h_out[((size_t)(batchA + 1) * Tq + t) * Hq + gunit] = hnew;
            if (t + 1 < Tq) {
                unsigned hu = __float_as_uint(hnew);
                unsigned f0 = __shfl_sync(0xFFFFFFFFu, hu, 0);
                unsigned f1 = __shfl_sync(0xFFFFFFFFu, hu, 1);
                unsigned f2 = __shfl_sync(0xFFFFFFFFu, hu, 2);
                unsigned f3 = __shfl_sync(0xFFFFFFFFu, hu, 3);
                if (sender && bsel == 1)
                    ST_ASYNC_V4(peer_h[q], f0, f1, f2, f3, peer_mb[q]);
            }
            curB = nxtB;
        }
    }
    cluster.sync();
}

// ---------------- no-op spacer (aligns ncu -s 5 onto scan1) ----------------
__global__ void noop_k() {}

// ---------------- attention (last query row only) ----------------
__global__ __launch_bounds__(256) void attn_last(
    const float* __restrict__ qkv_w, const float* __restrict__ qkv_b)
{
    __shared__ float q[64];
    __shared__ float sc[Tq];
    __shared__ float red[256];
    __shared__ float vp[256];
    const int bh = blockIdx.x;
    const int b = bh >> 3, h = bh & 7;
    const int tid = threadIdx.x;

    if (tid < 64) {
        int row = h * 64 + tid;
        const float* wr = qkv_w + (size_t)row * Dq;
        const float* ml = g_h2 + ((size_t)b * Tq + (Tq - 1)) * Hq;
        const float* mc = g_cv + ((size_t)b * Tq + (Tq - 1)) * Hq;
        float acc = qkv_b[row];
        for (int k = 0; k < 256; k++) acc = fmaf(ml[k], wr[k], acc);
        for (int k = 0; k < 256; k++) acc = fmaf(mc[k], wr[256 + k], acc);
        q[tid] = acc * 0.125f;
    }
    __syncthreads();

    float lmax = -1e30f;
    for (int t = tid; t < Tq; t += 256) {
        const float4* kp = (const float4*)(g_kv + ((size_t)b * Tq + t) * G4q + h * 64);
        float s = 0.f;
#pragma unroll
        for (int d4 = 0; d4 < 16; d4++) {
            float4 kk = kp[d4];
            float4 qq = ((const float4*)q)[d4];
            s += kk.x * qq.x + kk.y * qq.y + kk.z * qq.z + kk.w * qq.w;
        }
        sc[t] = s;
        lmax = fmaxf(lmax, s);
    }
    red[tid] = lmax; __syncthreads();
    for (int s2 = 128; s2 > 0; s2 >>= 1) {
        if (tid < s2) red[tid] = fmaxf(red[tid], red[tid + s2]);
        __syncthreads();
    }
    float m = red[0];
    __syncthreads();

    float lsum = 0.f;
    for (int t = tid; t < Tq; t += 256) {
        float pe = __expf(sc[t] - m);
        sc[t] = pe;
        lsum += pe;
    }
    red[tid] = lsum; __syncthreads();
    for (int s2 = 128; s2 > 0; s2 >>= 1) {
        if (tid < s2) red[tid] += red[tid + s2];
        __syncthreads();
    }
    float denom = red[0];
    __syncthreads();

    const int d = tid & 63, gg = tid >> 6;
    float acc = 0.f;
    for (int t = gg * 512; t < (gg + 1) * 512; t++)
        acc = fmaf(sc[t], g_kv[((size_t)b * Tq + t) * G4q + 512 + h * 64 + d], acc);
    vp[tid] = acc; __syncthreads();
    if (tid < 64) {
        float o = (vp[tid] + vp[64 + tid] + vp[128 + tid] + vp[192 + tid]) / denom;
        g_at[b * Dq + h * 64 + tid] = o;
    }
}

// ---------------- head ----------------
__global__ __launch_bounds__(512) void head_kernel(
    const float* __restrict__ pw, const float* __restrict__ pb,
    const float* __restrict__ lng, const float* __restrict__ lnb,
    const float* __restrict__ f1w, const float* __restrict__ f1b,
    const float* __restrict__ f2w, const float* __restrict__ f2b,
    float* __restrict__ out)
{
    __shared__ float a[Dq], zn[Dq], z2[Hq], red[512];
    const int b = blockIdx.x, tid = threadIdx.x;
    a[tid] = g_at[b * Dq + tid];
    __syncthreads();

    float acc = pb[tid];
    const float* wr = pw + (size_t)tid * Dq;
    for (int k = 0; k < Dq; k++) acc = fmaf(a[k], wr[k], acc);
    float mrg = (tid < 256) ? g_h2[((size_t)b * Tq + Tq - 1) * Hq + tid]
                            : g_cv[((size_t)b * Tq + Tq - 1) * Hq + tid - 256];
    float z = acc + mrg;

    red[tid] = z; __syncthreads();
    for (int s = 256; s > 0; s >>= 1) {
        if (tid < s) red[tid] += red[tid + s];
        __syncthreads();
    }
    float mu = red[0] / 512.f;
    __syncthreads();
    float dv = z - mu;
    red[tid] = dv * dv; __syncthreads();
    for (int s = 256; s > 0; s >>= 1) {
        if (tid < s) red[tid] += red[tid + s];
        __syncthreads();
    }
    float var = red[0] / 512.f;
    __syncthreads();

    zn[tid] = dv * rsqrtf(var + EPSq) * lng[tid] + lnb[tid];
    __syncthreads();

    if (tid < 256) {
        float a2 = f1b[tid];
        const float* w1 = f1w + (size_t)tid * Dq;
        for (int k = 0; k < Dq; k++) a2 = fmaf(zn[k], w1[k], a2);
        z2[tid] = a2 / (1.f + expf(-a2));
    }
    __syncthreads();

    if (tid < 3) {
        float lg = f2b[tid];
        const float* w2 = f2w + tid * 256;
        for (int j = 0; j < 256; j++) lg = fmaf(z2[j], w2[j], lg);
        if (tid == 0)      out[b]     = tanhf(lg);
        else if (tid == 1) out[4 + b] = (lg > 20.f) ? lg : log1pf(expf(lg));
        else               out[8 + b] = 1.f / (1.f + expf(-lg));
    }
}

// ---------------- launch ----------------
extern "C" void kernel_launch(void* const* d_in, const int* in_sizes, int n_in,
                              void* d_out, int out_size) {
    const float* x     = (const float*)d_in[0];
    const float* wih0  = (const float*)d_in[1];
    const float* whh0  = (const float*)d_in[2];
    const float* bih0  = (const float*)d_in[3];
    const float* bhh0  = (const float*)d_in[4];
    const float* wih1  = (const float*)d_in[5];
    const float* whh1  = (const float*)d_in[6];
    const float* bih1  = (const float*)d_in[7];
    const float* bhh1  = (const float*)d_in[8];
    const float* cw    = (const float*)d_in[9];
    const float* cb    = (const float*)d_in[10];
    const float* bng   = (const float*)d_in[11];
    const float* bnb   = (const float*)d_in[12];
    const float* bnm   = (const float*)d_in[13];
    const float* bnv   = (const float*)d_in[14];
    const float* qkvw  = (const float*)d_in[15];
    const float* qkvb  = (const float*)d_in[16];
    const float* pw    = (const float*)d_in[17];
    const float* pbv   = (const float*)d_in[18];
    const float* lng   = (const float*)d_in[19];
    const float* lnb   = (const float*)d_in[20];
    const float* f1w   = (const float*)d_in[21];
    const float* f1b   = (const float*)d_in[22];
    const float* f2w   = (const float*)d_in[23];
    const float* f2b   = (const float*)d_in[24];
    float* out = (float*)d_out;

    float *gx0, *gx1, *h1, *h2, *cv, *kv;
    cudaGetSymbolAddress((void**)&gx0, g_gx0);
    cudaGetSymbolAddress((void**)&gx1, g_gx1);
    cudaGetSymbolAddress((void**)&h1,  g_h1);
    cudaGetSymbolAddress((void**)&h2,  g_h2);
    cudaGetSymbolAddress((void**)&cv,  g_cv);
    cudaGetSymbolAddress((void**)&kv,  g_kv);

    const int conv_smem = (36 * 64 + 64 * 321) * 4;
    cudaFuncSetAttribute(conv_bn_silu, cudaFuncAttributeMaxDynamicSharedMemorySize, conv_smem);

    // 0: gx0 = x @ w_ih0^T + b_ih0 + b_hh0
    gemm128<<<dim3(64, 16), 256>>>(x, nullptr, 64, 64, wih0, bih0, bhh0, gx0, G4q);
    // 1: conv branch (independent of LSTM)
    conv_bn_silu<<<dim3(64, 4, 4), 256, conv_smem>>>(x, cw, cb, bng, bnb, bnm, bnv);
    // 2: layer-0 scan: 2 clusters x 8 CTAs, 2 batches per cluster
    lstm_scan<<<16, 256>>>(gx0, whh0, h1);
    // 3: gx1 = h1 @ w_ih1^T + b_ih1 + b_hh1
    gemm128<<<dim3(64, 16), 256>>>(h1, nullptr, 256, 256, wih1, bih1, bhh1, gx1, G4q);
    // 4: spacer so ncu (-s 5 -c 1) captures the scan next
    noop_k<<<1, 32>>>();
    // 5: layer-1 scan  <-- profiled launch
    lstm_scan<<<16, 256>>>(gx1, whh1, h2);
    // 6: kv = merged @ qkv_w[512:1536]^T + qkv_b[512:1536]
    gemm128<<<dim3(64, 16), 256>>>(h2, cv, 256, 512, qkvw + 512 * 512, qkvb + 512,
                                   nullptr, kv, G4q);
    // 7: attention (last row only)
    attn_last<<<32, 256>>>(qkvw, qkvb);
    // 8: head
    head_kernel<<<4, 512>>>(pw, pbv, lng, lnb, f1w, f1b, f2w, f2b, out);
}

// round 12
// speedup vs baseline: 1.4170x; 1.4170x over previous
#include <cuda_runtime.h>
#include <cooperative_groups.h>
#include <math.h>

namespace cg = cooperative_groups;

#define Bq   4
#define Tq   2048
#define INq  64
#define Hq   256
#define Dq   512
#define G4q  1024
#define EPSq 1e-5f

// ---------------- static scratch ----------------
__device__ float g_gx0[Bq * Tq * G4q];
__device__ float g_gx1[Bq * Tq * G4q];
__device__ float g_h1 [Bq * Tq * Hq];
__device__ float g_h2 [Bq * Tq * Hq];
__device__ float g_cv [Bq * Tq * Hq];
__device__ float g_kv [Bq * Tq * G4q];
__device__ float g_at [Bq * Dq];

#define FMA_F32X2(d, a, b, c) \
    asm("fma.rn.f32x2 %0, %1, %2, %3;" : "=l"(d) : "l"(a), "l"(b), "l"(c))

__device__ __forceinline__ float hsum_f32x2(unsigned long long v) {
    float lo, hi;
    asm("mov.b64 {%0, %1}, %2;" : "=f"(lo), "=f"(hi) : "l"(v));
    return lo + hi;
}

// single-MUFU tanh (sm_75+); sigmoid via tanh identity
__device__ __forceinline__ float tanha(float x) {
    float y; asm("tanh.approx.f32 %0, %1;" : "=f"(y) : "f"(x)); return y;
}
__device__ __forceinline__ float sigt(float x) {
    return fmaf(0.5f, tanha(0.5f * x), 0.5f);
}

// ---------------- GEMM 128x64 tiles ----------------
__global__ __launch_bounds__(256) void gemm128(
    const float* __restrict__ A1, const float* __restrict__ A2,
    int Ksplit, int K,
    const float* __restrict__ W, const float* __restrict__ b1,
    const float* __restrict__ b2, float* __restrict__ out, int N)
{
    __shared__ float As[16][128];
    __shared__ float Bs[16][64];
    const int m0 = blockIdx.x * 128, n0 = blockIdx.y * 64;
    const int tid = threadIdx.x;
    const int tx = tid & 15, ty = tid >> 4;
    const int lmA = tid & 127, khA = (tid >> 7) * 8;
    const int lnB = tid & 63,  kB  = (tid >> 6) * 4;
    const int K2 = K - Ksplit;

    float acc[8][4];
#pragma unroll
    for (int i = 0; i < 8; i++)
#pragma unroll
        for (int j = 0; j < 4; j++) acc[i][j] = 0.f;

    for (int k0 = 0; k0 < K; k0 += 16) {
        {
            int m = m0 + lmA;
#pragma unroll
            for (int half = 0; half < 2; half++) {
                int off = khA + half * 4;
                int kg = k0 + off;
                float4 v;
                if (kg < Ksplit) v = *(const float4*)(A1 + (size_t)m * Ksplit + kg);
                else             v = *(const float4*)(A2 + (size_t)m * K2 + (kg - Ksplit));
                As[off + 0][lmA] = v.x; As[off + 1][lmA] = v.y;
                As[off + 2][lmA] = v.z; As[off + 3][lmA] = v.w;
            }
            int n = n0 + lnB;
            float4 wv = *(const float4*)(W + (size_t)n * K + k0 + kB);
            Bs[kB + 0][lnB] = wv.x; Bs[kB + 1][lnB] = wv.y;
            Bs[kB + 2][lnB] = wv.z; Bs[kB + 3][lnB] = wv.w;
        }
        __syncthreads();
#pragma unroll
        for (int kk = 0; kk < 16; kk++) {
            float4 a0 = *(const float4*)&As[kk][ty * 8];
            float4 a1 = *(const float4*)&As[kk][ty * 8 + 4];
            float4 b  = *(const float4*)&Bs[kk][tx * 4];
            float av[8] = {a0.x, a0.y, a0.z, a0.w, a1.x, a1.y, a1.z, a1.w};
#pragma unroll
            for (int i = 0; i < 8; i++) {
                acc[i][0] = fmaf(av[i], b.x, acc[i][0]);
                acc[i][1] = fmaf(av[i], b.y, acc[i][1]);
                acc[i][2] = fmaf(av[i], b.z, acc[i][2]);
                acc[i][3] = fmaf(av[i], b.w, acc[i][3]);
            }
        }
        __syncthreads();
    }

    float bias[4];
#pragma unroll
    for (int j = 0; j < 4; j++) {
        int n = n0 + tx * 4 + j;
        bias[j] = b1[n] + (b2 ? b2[n] : 0.f);
    }
#pragma unroll
    for (int i = 0; i < 8; i++) {
        int m = m0 + ty * 8 + i;
        float4 r = make_float4(acc[i][0] + bias[0], acc[i][1] + bias[1],
                               acc[i][2] + bias[2], acc[i][3] + bias[3]);
        *(float4*)(out + (size_t)m * N + n0 + tx * 4) = r;
    }
}

// ---------------- conv1d(K=5,same) + BN + SiLU ----------------
__global__ __launch_bounds__(256, 1) void conv_bn_silu(
    const float* __restrict__ x, const float* __restrict__ cw,
    const float* __restrict__ cb, const float* __restrict__ bg,
    const float* __restrict__ bnb, const float* __restrict__ bmean,
    const float* __restrict__ bvar)
{
    extern __shared__ float sm[];
    float* xs = sm;              // [36][64]
    float* ws = sm + 36 * 64;    // [64][321]
    const int b = blockIdx.z;
    const int t0 = blockIdx.x * 32;
    const int ocb = blockIdx.y * 64;
    const int tid = threadIdx.x;

    for (int idx = tid; idx < 36 * 64; idx += 256) {
        int tr = idx >> 6, i = idx & 63;
        int tg = t0 + tr - 2;
        xs[idx] = (tg >= 0 && tg < Tq) ? x[((size_t)b * Tq + tg) * INq + i] : 0.f;
    }
    for (int idx = tid; idx < 64 * 320; idx += 256) {
        int o = idx / 320, ik = idx % 320;
        ws[o * 321 + ik] = cw[(size_t)(ocb + o) * 320 + ik];
    }
    __syncthreads();

    const int o = tid & 63, gq = tid >> 6;
    const int tb = gq * 8;
    float acc[8];
#pragma unroll
    for (int t = 0; t < 8; t++) acc[t] = 0.f;

    for (int i = 0; i < 64; i++) {
        float xv[12];
#pragma unroll
        for (int j = 0; j < 12; j++) xv[j] = xs[(tb + j) * 64 + i];
#pragma unroll
        for (int k = 0; k < 5; k++) {
            float wv = ws[o * 321 + i * 5 + k];
#pragma unroll
            for (int t = 0; t < 8; t++) acc[t] = fmaf(xv[t + k], wv, acc[t]);
        }
    }
    const int oc = ocb + o;
    float scl = rsqrtf(bvar[oc] + EPSq) * bg[oc];
    float sh = bnb[oc] - bmean[oc] * scl;
    float cbv = cb[oc];
#pragma unroll
    for (int t = 0; t < 8; t++) {
        float y = (acc[t] + cbv) * scl + sh;
        g_cv[((size_t)b * Tq + t0 + tb + t) * Hq + oc] = y / (1.f + __expf(-y));
    }
}

// ---------------- mbarrier / st.async helpers ----------------
#define MBAR_WAIT_ACQ_CLUSTER(addr, par) do {                                    \
    unsigned _done;                                                              \
    asm volatile("{\n\t.reg .pred P;\n\t"                                        \
        "mbarrier.try_wait.parity.acquire.cluster.shared::cta.b64 P, [%1], %2;\n\t" \
        "selp.b32 %0, 1, 0, P;\n\t}"                                             \
        : "=r"(_done) : "r"(addr), "r"(par) : "memory");                         \
    while (!_done) {                                                             \
        asm volatile("{\n\t.reg .pred P;\n\t"                                    \
            "mbarrier.try_wait.parity.acquire.cluster.shared::cta.b64 P, [%1], %2, 0x989680;\n\t" \
            "selp.b32 %0, 1, 0, P;\n\t}"                                         \
            : "=r"(_done) : "r"(addr), "r"(par) : "memory");                     \
    }                                                                            \
} while (0)

#define MBAR_ARM(addr, bytes) \
    asm volatile("mbarrier.arrive.expect_tx.shared.b64 _, [%0], %1;"             \
                 :: "r"(addr), "r"(bytes) : "memory")

#define ST_ASYNC_V4(daddr, r0, r1, r2, r3, mbaraddr) \
    asm volatile("st.async.weak.shared::cluster.mbarrier::complete_tx::bytes.v4.b32 " \
                 "[%0], {%1, %2, %3, %4}, [%5];"                                 \
                 :: "r"(daddr), "r"(r0), "r"(r1), "r"(r2), "r"(r3),              \
                    "r"(mbaraddr) : "memory")

__device__ __forceinline__ uint32_t smem_u32(const void* p) {
    uint32_t a;
    asm("{ .reg .u64 t; cvta.to.shared.u64 t, %1; cvt.u32.u64 %0, t; }"
        : "=r"(a) : "l"(p));
    return a;
}
__device__ __forceinline__ uint32_t mapa_u32(uint32_t a, int r) {
    uint32_t o;
    asm("mapa.shared::cluster.u32 %0, %1, %2;" : "=r"(o) : "r"(a), "r"(r));
    return o;
}

// ---------------- LSTM scan: 4 clusters x 8 CTAs, one batch per cluster --------
// Register-resident packed weights; warp-local gates (MUFU.TANH);
// h broadcast: per warp, lanes 0-7 each send ONE st.async.v4.b32 (16B = the
// warp's 4 units) to dest CTA = lane id. 64 messages per dest per step.
__global__ void __cluster_dims__(8, 1, 1) __launch_bounds__(256, 1) lstm_scan(
    const float* __restrict__ gx, const float* __restrict__ w_hh,
    float* __restrict__ h_out)
{
    __shared__ alignas(16) float h2s[2][256];
    __shared__ alignas(16) unsigned long long mbars[2];

    cg::cluster_group cluster = cg::this_cluster();
    const int rank  = (int)cluster.block_rank();
    const int batch = blockIdx.x >> 3;
    const int tid = threadIdx.x;
    const int w = tid >> 5, l = tid & 31;
    const int v  = l & 3;
    const int g  = (l >> 2) & 3;
    const int kh = l >> 4;
    const int gunit = rank * 32 + w * 4 + v;     // global hidden unit 0..255
    const int row = g * Hq + gunit;              // gate row 0..1023

    // this thread's 128 weights, packed as 64 x f32x2 (pairs along k)
    unsigned long long wreg[64];
    {
        const ulonglong2* wp = (const ulonglong2*)(w_hh + (size_t)row * Hq + (kh << 7));
#pragma unroll
        for (int i = 0; i < 32; i++) {
            ulonglong2 t2 = wp[i];
            wreg[2 * i]     = t2.x;
            wreg[2 * i + 1] = t2.y;
        }
    }

    if (tid < 256) { h2s[0][tid] = 0.f; h2s[1][tid] = 0.f; }

    const uint32_t mb0 = smem_u32(&mbars[0]);
    const uint32_t mb1 = smem_u32(&mbars[1]);
    if (tid == 0) {
        asm volatile("mbarrier.init.shared.b64 [%0], 1;" :: "r"(mb0) : "memory");
        asm volatile("mbarrier.init.shared.b64 [%0], 1;" :: "r"(mb1) : "memory");
        // arm step 1 (mbars[1]) and step 2 (mbars[0]); each phase = 1024 bytes
        MBAR_ARM(mb1, 1024);
        MBAR_ARM(mb0, 1024);
    }

    // dest addresses: lane l (l<8) sends this warp's 4-unit block to CTA l
    const uint32_t h0_local = smem_u32(&h2s[0][0]);
    const int dest = l & 7;
    uint32_t peer_h[2], peer_mb[2];
    {
        uint32_t base = mapa_u32(h0_local, dest);
        uint32_t blk = (uint32_t)((rank * 32 + w * 4) * 4);   // 16B-aligned
        peer_h[0] = base + blk;
        peer_h[1] = base + 1024u + blk;
        peer_mb[0] = mapa_u32(mb0, dest);
        peer_mb[1] = mapa_u32(mb1, dest);
    }

    cluster.sync();

    const float* gx_row = gx + (size_t)batch * Tq * G4q + row;
    const bool write_out = ((l >> 2) == rank);   // 4 lanes/warp write h_out
    const bool sender = (l < 8);
    float c0 = 0.f;
    float cur = gx_row[0];

    for (int t = 0; t < Tq; t++) {
        // prefetch next-step gx before waiting (hides DRAM latency)
        float nxt = 0.f;
        if (t + 1 < Tq) nxt = gx_row[(size_t)(t + 1) * G4q];

        if (t > 0) {
            const uint32_t mb = (t & 1) ? mb1 : mb0;
            unsigned par = (unsigned)(((t >> 1) + ((t & 1) ^ 1)) & 1);
            MBAR_WAIT_ACQ_CLUSTER(mb, par);
            // re-arm for step t+2 (safe: arm precedes this CTA's h(t+1) sends,
            // and producers need all h(t+1) before storing t+2 data here)
            if (tid == 0 && t + 2 < Tq) MBAR_ARM(mb, 1024);
        }
        const int p = t & 1;
        const ulonglong2* hb2 = (const ulonglong2*)&h2s[p][kh << 7];

        // matvec: 64 packed f32x2 FMAs, 4 independent chains
        unsigned long long acc0 = 0ull, acc1 = 0ull, acc2 = 0ull, acc3 = 0ull;
#pragma unroll
        for (int i = 0; i < 32; i += 2) {
            ulonglong2 hv0 = hb2[i];
            ulonglong2 hv1 = hb2[i + 1];
            FMA_F32X2(acc0, wreg[2 * i + 0], hv0.x, acc0);
            FMA_F32X2(acc1, wreg[2 * i + 1], hv0.y, acc1);
            FMA_F32X2(acc2, wreg[2 * i + 2], hv1.x, acc2);
            FMA_F32X2(acc3, wreg[2 * i + 3], hv1.y, acc3);
        }
        float partial = (hsum_f32x2(acc0) + hsum_f32x2(acc1))
                      + (hsum_f32x2(acc2) + hsum_f32x2(acc3));
        // combine k-halves (lanes l and l^16 hold the two halves of same row)
        float sum = partial + __shfl_xor_sync(0xFFFFFFFFu, partial, 16);
        sum += cur;   // gx for this row

        // gather the 4 gate sums of unit v (lanes v, v+4, v+8, v+12)
        float si = __shfl_sync(0xFFFFFFFFu, sum, v);
        float sf = __shfl_sync(0xFFFFFFFFu, sum, v + 4);
        float sg = __shfl_sync(0xFFFFFFFFu, sum, v + 8);
        float so = __shfl_sync(0xFFFFFFFFu, sum, v + 12);

        // every lane redundantly computes h(unit v) — single-MUFU tanh path
        c0 = sigt(sf) * c0 + sigt(si) * tanha(sg);
        float hnew = sigt(so) * tanha(c0);

        if (write_out)
            h_out[((size_t)batch * Tq + t) * Hq + gunit] = hnew;

        if (t + 1 < Tq) {
            // broadcast the warp's 4 unit values to all lanes
            unsigned hu = __float_as_uint(hnew);
            unsigned f0 = __shfl_sync(0xFFFFFFFFu, hu, 0);
            unsigned f1 = __shfl_sync(0xFFFFFFFFu, hu, 1);
            unsigned f2 = __shfl_sync(0xFFFFFFFFu, hu, 2);
            unsigned f3 = __shfl_sync(0xFFFFFFFFu, hu, 3);
            if (sender) {
                const int q = (t + 1) & 1;
                ST_ASYNC_V4(peer_h[q], f0, f1, f2, f3, peer_mb[q]);
            }
        }
        cur = nxt;
    }
    cluster.sync();
}

// ---------------- no-op spacer (aligns ncu -s 5 onto scan1) ----------------
__global__ void noop_k() {}

// ---------------- attention (last query row only) ----------------
__global__ __launch_bounds__(256) void attn_last(
    const float* __restrict__ qkv_w, const float* __restrict__ qkv_b)
{
    __shared__ float q[64];
    __shared__ float sc[Tq];
    __shared__ float red[256];
    __shared__ float vp[256];
    const int bh = blockIdx.x;
    const int b = bh >> 3, h = bh & 7;
    const int tid = threadIdx.x;

    if (tid < 64) {
        int row = h * 64 + tid;
        const float* wr = qkv_w + (size_t)row * Dq;
        const float* ml = g_h2 + ((size_t)b * Tq + (Tq - 1)) * Hq;
        const float* mc = g_cv + ((size_t)b * Tq + (Tq - 1)) * Hq;
        float acc = qkv_b[row];
        for (int k = 0; k < 256; k++) acc = fmaf(ml[k], wr[k], acc);
        for (int k = 0; k < 256; k++) acc = fmaf(mc[k], wr[256 + k], acc);
        q[tid] = acc * 0.125f;
    }
    __syncthreads();

    float lmax = -1e30f;
    for (int t = tid; t < Tq; t += 256) {
        const float4* kp = (const float4*)(g_kv + ((size_t)b * Tq + t) * G4q + h * 64);
        float s = 0.f;
#pragma unroll
        for (int d4 = 0; d4 < 16; d4++) {
            float4 kk = kp[d4];
            float4 qq = ((const float4*)q)[d4];
            s += kk.x * qq.x + kk.y * qq.y + kk.z * qq.z + kk.w * qq.w;
        }
        sc[t] = s;
        lmax = fmaxf(lmax, s);
    }
    red[tid] = lmax; __syncthreads();
    for (int s2 = 128; s2 > 0; s2 >>= 1) {
        if (tid < s2) red[tid] = fmaxf(red[tid], red[tid + s2]);
        __syncthreads();
    }
    float m = red[0];
    __syncthreads();

    float lsum = 0.f;
    for (int t = tid; t < Tq; t += 256) {
        float pe = __expf(sc[t] - m);
        sc[t] = pe;
        lsum += pe;
    }
    red[tid] = lsum; __syncthreads();
    for (int s2 = 128; s2 > 0; s2 >>= 1) {
        if (tid < s2) red[tid] += red[tid + s2];
        __syncthreads();
    }
    float denom = red[0];
    __syncthreads();

    const int d = tid & 63, gg = tid >> 6;
    float acc = 0.f;
    for (int t = gg * 512; t < (gg + 1) * 512; t++)
        acc = fmaf(sc[t], g_kv[((size_t)b * Tq + t) * G4q + 512 + h * 64 + d], acc);
    vp[tid] = acc; __syncthreads();
    if (tid < 64) {
        float o = (vp[tid] + vp[64 + tid] + vp[128 + tid] + vp[192 + tid]) / denom;
        g_at[b * Dq + h * 64 + tid] = o;
    }
}

// ---------------- head ----------------
__global__ __launch_bounds__(512) void head_kernel(
    const float* __restrict__ pw, const float* __restrict__ pb,
    const float* __restrict__ lng, const float* __restrict__ lnb,
    const float* __restrict__ f1w, const float* __restrict__ f1b,
    const float* __restrict__ f2w, const float* __restrict__ f2b,
    float* __restrict__ out)
{
    __shared__ float a[Dq], zn[Dq], z2[Hq], red[512];
    const int b = blockIdx.x, tid = threadIdx.x;
    a[tid] = g_at[b * Dq + tid];
    __syncthreads();

    float acc = pb[tid];
    const float* wr = pw + (size_t)tid * Dq;
    for (int k = 0; k < Dq; k++) acc = fmaf(a[k], wr[k], acc);
    float mrg = (tid < 256) ? g_h2[((size_t)b * Tq + Tq - 1) * Hq + tid]
                            : g_cv[((size_t)b * Tq + Tq - 1) * Hq + tid - 256];
    float z = acc + mrg;

    red[tid] = z; __syncthreads();
    for (int s = 256; s > 0; s >>= 1) {
        if (tid < s) red[tid] += red[tid + s];
        __syncthreads();
    }
    float mu = red[0] / 512.f;
    __syncthreads();
    float dv = z - mu;
    red[tid] = dv * dv; __syncthreads();
    for (int s = 256; s > 0; s >>= 1) {
        if (tid < s) red[tid] += red[tid + s];
        __syncthreads();
    }
    float var = red[0] / 512.f;
    __syncthreads();

    zn[tid] = dv * rsqrtf(var + EPSq) * lng[tid] + lnb[tid];
    __syncthreads();

    if (tid < 256) {
        float a2 = f1b[tid];
        const float* w1 = f1w + (size_t)tid * Dq;
        for (int k = 0; k < Dq; k++) a2 = fmaf(zn[k], w1[k], a2);
        z2[tid] = a2 / (1.f + expf(-a2));
    }
    __syncthreads();

    if (tid < 3) {
        float lg = f2b[tid];
        const float* w2 = f2w + tid * 256;
        for (int j = 0; j < 256; j++) lg = fmaf(z2[j], w2[j], lg);
        if (tid == 0)      out[b]     = tanhf(lg);
        else if (tid == 1) out[4 + b] = (lg > 20.f) ? lg : log1pf(expf(lg));
        else               out[8 + b] = 1.f / (1.f + expf(-lg));
    }
}

// ---------------- launch ----------------
extern "C" void kernel_launch(void* const* d_in, const int* in_sizes, int n_in,
                              void* d_out, int out_size) {
    const float* x     = (const float*)d_in[0];
    const float* wih0  = (const float*)d_in[1];
    const float* whh0  = (const float*)d_in[2];
    const float* bih0  = (const float*)d_in[3];
    const float* bhh0  = (const float*)d_in[4];
    const float* wih1  = (const float*)d_in[5];
    const float* whh1  = (const float*)d_in[6];
    const float* bih1  = (const float*)d_in[7];
    const float* bhh1  = (const float*)d_in[8];
    const float* cw    = (const float*)d_in[9];
    const float* cb    = (const float*)d_in[10];
    const float* bng   = (const float*)d_in[11];
    const float* bnb   = (const float*)d_in[12];
    const float* bnm   = (const float*)d_in[13];
    const float* bnv   = (const float*)d_in[14];
    const float* qkvw  = (const float*)d_in[15];
    const float* qkvb  = (const float*)d_in[16];
    const float* pw    = (const float*)d_in[17];
    const float* pbv   = (const float*)d_in[18];
    const float* lng   = (const float*)d_in[19];
    const float* lnb   = (const float*)d_in[20];
    const float* f1w   = (const float*)d_in[21];
    const float* f1b   = (const float*)d_in[22];
    const float* f2w   = (const float*)d_in[23];
    const float* f2b   = (const float*)d_in[24];
    float* out = (float*)d_out;

    float *gx0, *gx1, *h1, *h2, *cv, *kv;
    cudaGetSymbolAddress((void**)&gx0, g_gx0);
    cudaGetSymbolAddress((void**)&gx1, g_gx1);
    cudaGetSymbolAddress((void**)&h1,  g_h1);
    cudaGetSymbolAddress((void**)&h2,  g_h2);
    cudaGetSymbolAddress((void**)&cv,  g_cv);
    cudaGetSymbolAddress((void**)&kv,  g_kv);

    const int conv_smem = (36 * 64 + 64 * 321) * 4;
    cudaFuncSetAttribute(conv_bn_silu, cudaFuncAttributeMaxDynamicSharedMemorySize, conv_smem);

    // 0: gx0 = x @ w_ih0^T + b_ih0 + b_hh0
    gemm128<<<dim3(64, 16), 256>>>(x, nullptr, 64, 64, wih0, bih0, bhh0, gx0, G4q);
    // 1: conv branch (independent of LSTM)
    conv_bn_silu<<<dim3(64, 4, 4), 256, conv_smem>>>(x, cw, cb, bng, bnb, bnm, bnv);
    // 2: layer-0 scan: 4 clusters (one per batch) x 8 CTAs
    lstm_scan<<<32, 256>>>(gx0, whh0, h1);
    // 3: gx1 = h1 @ w_ih1^T + b_ih1 + b_hh1
    gemm128<<<dim3(64, 16), 256>>>(h1, nullptr, 256, 256, wih1, bih1, bhh1, gx1, G4q);
    // 4: spacer so ncu (-s 5 -c 1) captures the scan next
    noop_k<<<1, 32>>>();
    // 5: layer-1 scan  <-- profiled launch
    lstm_scan<<<32, 256>>>(gx1, whh1, h2);
    // 6: kv = merged @ qkv_w[512:1536]^T + qkv_b[512:1536]
    gemm128<<<dim3(64, 16), 256>>>(h2, cv, 256, 512, qkvw + 512 * 512, qkvb + 512,
                                   nullptr, kv, G4q);
    // 7: attention (last row only)
    attn_last<<<32, 256>>>(qkvw, qkvb);
    // 8: head
    head_kernel<<<4, 512>>>(pw, pbv, lng, lnb, f1w, f1b, f2w, f2b, out);
}

// round 13
// speedup vs baseline: 2.0769x; 1.4657x over previous
#include <cuda_runtime.h>
#include <cooperative_groups.h>
#include <math.h>

namespace cg = cooperative_groups;

#define Bq   4
#define Tq   2048
#define INq  64
#define Hq   256
#define Dq   512
#define G4q  1024
#define EPSq 1e-5f

// ---------------- static scratch ----------------
__device__ float g_gx0[Bq * Tq * G4q];
__device__ float g_gx1[Bq * Tq * G4q];
__device__ float g_h1 [Bq * Tq * Hq];
__device__ float g_h2 [Bq * Tq * Hq];
__device__ float g_cv [Bq * Tq * Hq];
__device__ float g_kv [Bq * Tq * G4q];
__device__ float g_at [Bq * Dq];

// chunk-ready flags: [0]=gx0 (target 4), [1]=h1 (target 8), [2]=gx1 (target 4)
__device__ int g_flags[3][Bq][16];

#define FMA_F32X2(d, a, b, c) \
    asm("fma.rn.f32x2 %0, %1, %2, %3;" : "=l"(d) : "l"(a), "l"(b), "l"(c))

__device__ __forceinline__ float hsum_f32x2(unsigned long long v) {
    float lo, hi;
    asm("mov.b64 {%0, %1}, %2;" : "=f"(lo), "=f"(hi) : "l"(v));
    return lo + hi;
}
__device__ __forceinline__ float tanha(float x) {
    float y; asm("tanh.approx.f32 %0, %1;" : "=f"(y) : "f"(x)); return y;
}
__device__ __forceinline__ float sigt(float x) {
    return fmaf(0.5f, tanha(0.5f * x), 0.5f);
}

// ---------------- mbarrier / st.async helpers ----------------
#define MBAR_WAIT_ACQ_CLUSTER(addr, par) do {                                    \
    unsigned _done;                                                              \
    asm volatile("{\n\t.reg .pred P;\n\t"                                        \
        "mbarrier.try_wait.parity.acquire.cluster.shared::cta.b64 P, [%1], %2;\n\t" \
        "selp.b32 %0, 1, 0, P;\n\t}"                                             \
        : "=r"(_done) : "r"(addr), "r"(par) : "memory");                         \
    while (!_done) {                                                             \
        asm volatile("{\n\t.reg .pred P;\n\t"                                    \
            "mbarrier.try_wait.parity.acquire.cluster.shared::cta.b64 P, [%1], %2, 0x989680;\n\t" \
            "selp.b32 %0, 1, 0, P;\n\t}"                                         \
            : "=r"(_done) : "r"(addr), "r"(par) : "memory");                     \
    }                                                                            \
} while (0)

#define MBAR_ARM(addr, bytes) \
    asm volatile("mbarrier.arrive.expect_tx.shared.b64 _, [%0], %1;"             \
                 :: "r"(addr), "r"(bytes) : "memory")

#define ST_ASYNC_V4(daddr, r0, r1, r2, r3, mbaraddr) \
    asm volatile("st.async.weak.shared::cluster.mbarrier::complete_tx::bytes.v4.b32 " \
                 "[%0], {%1, %2, %3, %4}, [%5];"                                 \
                 :: "r"(daddr), "r"(r0), "r"(r1), "r"(r2), "r"(r3),              \
                    "r"(mbaraddr) : "memory")

__device__ __forceinline__ uint32_t smem_u32(const void* p) {
    uint32_t a;
    asm("{ .reg .u64 t; cvta.to.shared.u64 t, %1; cvt.u32.u64 %0, t; }"
        : "=r"(a) : "l"(p));
    return a;
}
__device__ __forceinline__ uint32_t mapa_u32(uint32_t a, int r) {
    uint32_t o;
    asm("mapa.shared::cluster.u32 %0, %1, %2;" : "=r"(o) : "r"(a), "r"(r));
    return o;
}

// spin until *f >= target, then acquire
__device__ __forceinline__ void wait_flag(volatile int* f, int target) {
    if (*f < target) { while (*f < target) {} }
    __threadfence();
}

// ---------------- scan role (R8-proven structure + chunk gating) ----------------
__device__ __forceinline__ void scan_role(
    const float* __restrict__ gx, const float* __restrict__ w_hh,
    float* __restrict__ h_out, int batch,
    volatile int* in_ready, int in_target, int* out_ready, float* dsm)
{
    float* h2s = dsm;                                     // [2][256]
    unsigned long long* mbars = (unsigned long long*)(dsm + 512);

    cg::cluster_group cluster = cg::this_cluster();
    const int rank = (int)cluster.block_rank();
    const int tid = threadIdx.x;
    const int w = tid >> 5, l = tid & 31;
    const int v  = l & 3;
    const int g  = (l >> 2) & 3;
    const int kh = l >> 4;
    const int gunit = rank * 32 + w * 4 + v;
    const int row = g * Hq + gunit;

    unsigned long long wreg[64];
    {
        const ulonglong2* wp = (const ulonglong2*)(w_hh + (size_t)row * Hq + (kh << 7));
#pragma unroll
        for (int i = 0; i < 32; i++) {
            ulonglong2 t2 = wp[i];
            wreg[2 * i]     = t2.x;
            wreg[2 * i + 1] = t2.y;
        }
    }

    if (tid < 256) { h2s[tid] = 0.f; h2s[256 + tid] = 0.f; }

    const uint32_t mb0 = smem_u32(&mbars[0]);
    const uint32_t mb1 = smem_u32(&mbars[1]);
    if (tid == 0) {
        asm volatile("mbarrier.init.shared.b64 [%0], 1;" :: "r"(mb0) : "memory");
        asm volatile("mbarrier.init.shared.b64 [%0], 1;" :: "r"(mb1) : "memory");
        MBAR_ARM(mb1, 1024);
        MBAR_ARM(mb0, 1024);
    }

    const uint32_t h0_local = smem_u32(&h2s[0]);
    const int dest = l & 7;
    uint32_t peer_h[2], peer_mb[2];
    {
        uint32_t base = mapa_u32(h0_local, dest);
        uint32_t blk = (uint32_t)((rank * 32 + w * 4) * 4);
        peer_h[0] = base + blk;
        peer_h[1] = base + 1024u + blk;
        peer_mb[0] = mapa_u32(mb0, dest);
        peer_mb[1] = mapa_u32(mb1, dest);
    }

    cluster.sync();

    const float* gx_row = gx + (size_t)batch * Tq * G4q + row;
    const bool write_out = ((l >> 2) == rank);
    const bool sender = (l < 8);
    float c0 = 0.f;

    wait_flag(in_ready, in_target);        // gx chunk 0
    float cur = gx_row[0];

    for (int t = 0; t < Tq; t++) {
        if (t + 1 < Tq && ((t + 1) & 127) == 0)
            wait_flag(in_ready + ((t + 1) >> 7), in_target);   // next gx chunk
        float nxt = 0.f;
        if (t + 1 < Tq) nxt = gx_row[(size_t)(t + 1) * G4q];

        if (t > 0) {
            const uint32_t mb = (t & 1) ? mb1 : mb0;
            unsigned par = (unsigned)(((t >> 1) + ((t & 1) ^ 1)) & 1);
            MBAR_WAIT_ACQ_CLUSTER(mb, par);
            if (tid == 0 && t + 2 < Tq) MBAR_ARM(mb, 1024);
        }
        const int p = t & 1;
        const ulonglong2* hb2 = (const ulonglong2*)(h2s + (p << 8) + (kh << 7));

        unsigned long long acc0 = 0ull, acc1 = 0ull, acc2 = 0ull, acc3 = 0ull;
#pragma unroll
        for (int i = 0; i < 32; i += 2) {
            ulonglong2 hv0 = hb2[i];
            ulonglong2 hv1 = hb2[i + 1];
            FMA_F32X2(acc0, wreg[2 * i + 0], hv0.x, acc0);
            FMA_F32X2(acc1, wreg[2 * i + 1], hv0.y, acc1);
            FMA_F32X2(acc2, wreg[2 * i + 2], hv1.x, acc2);
            FMA_F32X2(acc3, wreg[2 * i + 3], hv1.y, acc3);
        }
        float partial = (hsum_f32x2(acc0) + hsum_f32x2(acc1))
                      + (hsum_f32x2(acc2) + hsum_f32x2(acc3));
        float sum = partial + __shfl_xor_sync(0xFFFFFFFFu, partial, 16);
        sum += cur;

        float si = __shfl_sync(0xFFFFFFFFu, sum, v);
        float sf = __shfl_sync(0xFFFFFFFFu, sum, v + 4);
        float sg = __shfl_sync(0xFFFFFFFFu, sum, v + 8);
        float so = __shfl_sync(0xFFFFFFFFu, sum, v + 12);

        c0 = sigt(sf) * c0 + sigt(si) * tanha(sg);
        float hnew = sigt(so) * tanha(c0);

        if (write_out)
            h_out[((size_t)batch * Tq + t) * Hq + gunit] = hnew;

        if (t + 1 < Tq) {
            unsigned hu = __float_as_uint(hnew);
            unsigned f0 = __shfl_sync(0xFFFFFFFFu, hu, 0);
            unsigned f1 = __shfl_sync(0xFFFFFFFFu, hu, 1);
            unsigned f2 = __shfl_sync(0xFFFFFFFFu, hu, 2);
            unsigned f3 = __shfl_sync(0xFFFFFFFFu, hu, 3);
            if (sender) {
                const int q = (t + 1) & 1;
                ST_ASYNC_V4(peer_h[q], f0, f1, f2, f3, peer_mb[q]);
            }
        }

        // publish h chunk (scan0 only): every thread fences its own writes,
        // block barrier, tid0 releases the counter
        if (out_ready && (t & 127) == 127) {
            __threadfence();
            __syncthreads();
            if (tid == 0) atomicAdd(out_ready + (t >> 7), 1);
        }
        cur = nxt;
    }
    cluster.sync();
}

// ---------------- 128x64 GEMM tile (SMEM from dsm) ----------------
__device__ __forceinline__ void tile_128x64(
    const float* __restrict__ A, int lda, const float* __restrict__ W, int K,
    const float* __restrict__ b1, const float* __restrict__ b2,
    float* __restrict__ out, int n0, float* sA, float* sB)
{
    const int tid = threadIdx.x;
    const int tx = tid & 15, ty = tid >> 4;
    const int lmA = tid & 127, khA = (tid >> 7) * 8;
    const int lnB = tid & 63,  kB  = (tid >> 6) * 4;

    float acc[8][4];
#pragma unroll
    for (int i = 0; i < 8; i++)
#pragma unroll
        for (int j = 0; j < 4; j++) acc[i][j] = 0.f;

    for (int k0 = 0; k0 < K; k0 += 16) {
#pragma unroll
        for (int half = 0; half < 2; half++) {
            int off = khA + half * 4;
            float4 vv = *(const float4*)(A + (size_t)lmA * lda + k0 + off);
            sA[(off + 0) * 128 + lmA] = vv.x; sA[(off + 1) * 128 + lmA] = vv.y;
            sA[(off + 2) * 128 + lmA] = vv.z; sA[(off + 3) * 128 + lmA] = vv.w;
        }
        float4 wv = *(const float4*)(W + (size_t)(n0 + lnB) * K + k0 + kB);
        sB[(kB + 0) * 64 + lnB] = wv.x; sB[(kB + 1) * 64 + lnB] = wv.y;
        sB[(kB + 2) * 64 + lnB] = wv.z; sB[(kB + 3) * 64 + lnB] = wv.w;
        __syncthreads();
#pragma unroll
        for (int kk = 0; kk < 16; kk++) {
            float4 a0 = *(const float4*)&sA[kk * 128 + ty * 8];
            float4 a1 = *(const float4*)&sA[kk * 128 + ty * 8 + 4];
            float4 b  = *(const float4*)&sB[kk * 64 + tx * 4];
            float av[8] = {a0.x, a0.y, a0.z, a0.w, a1.x, a1.y, a1.z, a1.w};
#pragma unroll
            for (int i = 0; i < 8; i++) {
                acc[i][0] = fmaf(av[i], b.x, acc[i][0]);
                acc[i][1] = fmaf(av[i], b.y, acc[i][1]);
                acc[i][2] = fmaf(av[i], b.z, acc[i][2]);
                acc[i][3] = fmaf(av[i], b.w, acc[i][3]);
            }
        }
        __syncthreads();
    }

    float bias[4];
#pragma unroll
    for (int j = 0; j < 4; j++) {
        int n = n0 + tx * 4 + j;
        bias[j] = b1[n] + b2[n];
    }
#pragma unroll
    for (int i = 0; i < 8; i++) {
        float4 r = make_float4(acc[i][0] + bias[0], acc[i][1] + bias[1],
                               acc[i][2] + bias[2], acc[i][3] + bias[3]);
        *(float4*)(out + (size_t)(ty * 8 + i) * G4q + n0 + tx * 4) = r;
    }
}

// ---------------- chunked gx gemm role ----------------
__device__ __forceinline__ void gemm_chunk_role(
    const float* __restrict__ A0, int lda, const float* __restrict__ W,
    const float* __restrict__ b1, const float* __restrict__ b2,
    float* __restrict__ out0, int K, int slice_n0,
    volatile int* in_ready, int in_target, int* out_ready, float* dsm)
{
    float* sA = dsm;          // [16][128]
    float* sB = dsm + 2048;   // [16][64]
    for (int c = 0; c < 16; c++) {
        if (in_ready) wait_flag(in_ready + c, in_target);
        const float* A = A0 + (size_t)c * 128 * lda;
        float* out = out0 + (size_t)c * 128 * G4q;
        for (int j = 0; j < 4; j++)
            tile_128x64(A, lda, W, K, b1, b2, out, slice_n0 + j * 64, sA, sB);
        __threadfence();
        __syncthreads();
        if (threadIdx.x == 0) atomicAdd(out_ready + c, 1);
    }
}

// ---------------- mega kernel: scans + chunked gx gemms, overlapped ----------
// grid = 96 CTAs (12 clusters x 8), 1 CTA/SM -> all co-resident.
// clusters 0-3: layer-0 scan (batch = cid); 4-7: layer-1 scan;
// CTAs 64-79: gx1 gemm (4 per batch); CTAs 80-95: gx0 gemm (4 per batch).
__global__ void __cluster_dims__(8, 1, 1) __launch_bounds__(256, 1) mega(
    const float* __restrict__ x,
    const float* __restrict__ wih0, const float* __restrict__ whh0,
    const float* __restrict__ bih0, const float* __restrict__ bhh0,
    const float* __restrict__ wih1, const float* __restrict__ whh1,
    const float* __restrict__ bih1, const float* __restrict__ bhh1,
    float* __restrict__ gx0, float* __restrict__ gx1,
    float* __restrict__ h1, float* __restrict__ h2)
{
    extern __shared__ float dsm[];
    const int cid = blockIdx.x >> 3;

    if (cid < 4) {
        scan_role(gx0, whh0, h1, cid,
                  (volatile int*)&g_flags[0][cid][0], 4,
                  &g_flags[1][cid][0], dsm);
    } else if (cid < 8) {
        scan_role(gx1, whh1, h2, cid - 4,
                  (volatile int*)&g_flags[2][cid - 4][0], 4,
                  nullptr, dsm);
    } else if (blockIdx.x < 80) {
        const int idx = blockIdx.x - 64;
        const int b = idx & 3, slice = idx >> 2;
        gemm_chunk_role(h1 + (size_t)b * Tq * Hq, Hq, wih1, bih1, bhh1,
                        gx1 + (size_t)b * Tq * G4q, Hq, slice * 256,
                        (volatile int*)&g_flags[1][b][0], 8,
                        &g_flags[2][b][0], dsm);
    } else {
        const int idx = blockIdx.x - 80;
        const int b = idx & 3, slice = idx >> 2;
        gemm_chunk_role(x + (size_t)b * Tq * INq, INq, wih0, bih0, bhh0,
                        gx0 + (size_t)b * Tq * G4q, INq, slice * 256,
                        nullptr, 0,
                        &g_flags[0][b][0], dsm);
    }
}

// ---------------- flag reset (graph-replay determinism) ----------------
__global__ void reset_flags() {
    ((int*)g_flags)[threadIdx.x] = 0;
}

// ---------------- GEMM 128x64 (standalone, for kv projection) ----------------
__global__ __launch_bounds__(256) void gemm128(
    const float* __restrict__ A1, const float* __restrict__ A2,
    int Ksplit, int K,
    const float* __restrict__ W, const float* __restrict__ b1,
    const float* __restrict__ b2, float* __restrict__ out, int N)
{
    __shared__ float As[16][128];
    __shared__ float Bs[16][64];
    const int m0 = blockIdx.x * 128, n0 = blockIdx.y * 64;
    const int tid = threadIdx.x;
    const int tx = tid & 15, ty = tid >> 4;
    const int lmA = tid & 127, khA = (tid >> 7) * 8;
    const int lnB = tid & 63,  kB  = (tid >> 6) * 4;
    const int K2 = K - Ksplit;

    float acc[8][4];
#pragma unroll
    for (int i = 0; i < 8; i++)
#pragma unroll
        for (int j = 0; j < 4; j++) acc[i][j] = 0.f;

    for (int k0 = 0; k0 < K; k0 += 16) {
        {
            int m = m0 + lmA;
#pragma unroll
            for (int half = 0; half < 2; half++) {
                int off = khA + half * 4;
                int kg = k0 + off;
                float4 v;
                if (kg < Ksplit) v = *(const float4*)(A1 + (size_t)m * Ksplit + kg);
                else             v = *(const float4*)(A2 + (size_t)m * K2 + (kg - Ksplit));
                As[off + 0][lmA] = v.x; As[off + 1][lmA] = v.y;
                As[off + 2][lmA] = v.z; As[off + 3][lmA] = v.w;
            }
            int n = n0 + lnB;
            float4 wv = *(const float4*)(W + (size_t)n * K + k0 + kB);
            Bs[kB + 0][lnB] = wv.x; Bs[kB + 1][lnB] = wv.y;
            Bs[kB + 2][lnB] = wv.z; Bs[kB + 3][lnB] = wv.w;
        }
        __syncthreads();
#pragma unroll
        for (int kk = 0; kk < 16; kk++) {
            float4 a0 = *(const float4*)&As[kk][ty * 8];
            float4 a1 = *(const float4*)&As[kk][ty * 8 + 4];
            float4 b  = *(const float4*)&Bs[kk][tx * 4];
            float av[8] = {a0.x, a0.y, a0.z, a0.w, a1.x, a1.y, a1.z, a1.w};
#pragma unroll
            for (int i = 0; i < 8; i++) {
                acc[i][0] = fmaf(av[i], b.x, acc[i][0]);
                acc[i][1] = fmaf(av[i], b.y, acc[i][1]);
                acc[i][2] = fmaf(av[i], b.z, acc[i][2]);
                acc[i][3] = fmaf(av[i], b.w, acc[i][3]);
            }
        }
        __syncthreads();
    }

    float bias[4];
#pragma unroll
    for (int j = 0; j < 4; j++) {
        int n = n0 + tx * 4 + j;
        bias[j] = b1[n] + (b2 ? b2[n] : 0.f);
    }
#pragma unroll
    for (int i = 0; i < 8; i++) {
        int m = m0 + ty * 8 + i;
        float4 r = make_float4(acc[i][0] + bias[0], acc[i][1] + bias[1],
                               acc[i][2] + bias[2], acc[i][3] + bias[3]);
        *(float4*)(out + (size_t)m * N + n0 + tx * 4) = r;
    }
}

// ---------------- conv1d(K=5,same) + BN + SiLU ----------------
__global__ __launch_bounds__(256, 1) void conv_bn_silu(
    const float* __restrict__ x, const float* __restrict__ cw,
    const float* __restrict__ cb, const float* __restrict__ bg,
    const float* __restrict__ bnb, const float* __restrict__ bmean,
    const float* __restrict__ bvar)
{
    extern __shared__ float sm[];
    float* xs = sm;              // [36][64]
    float* ws = sm + 36 * 64;    // [64][321]
    const int b = blockIdx.z;
    const int t0 = blockIdx.x * 32;
    const int ocb = blockIdx.y * 64;
    const int tid = threadIdx.x;

    for (int idx = tid; idx < 36 * 64; idx += 256) {
        int tr = idx >> 6, i = idx & 63;
        int tg = t0 + tr - 2;
        xs[idx] = (tg >= 0 && tg < Tq) ? x[((size_t)b * Tq + tg) * INq + i] : 0.f;
    }
    for (int idx = tid; idx < 64 * 320; idx += 256) {
        int o = idx / 320, ik = idx % 320;
        ws[o * 321 + ik] = cw[(size_t)(ocb + o) * 320 + ik];
    }
    __syncthreads();

    const int o = tid & 63, gq = tid >> 6;
    const int tb = gq * 8;
    float acc[8];
#pragma unroll
    for (int t = 0; t < 8; t++) acc[t] = 0.f;

    for (int i = 0; i < 64; i++) {
        float xv[12];
#pragma unroll
        for (int j = 0; j < 12; j++) xv[j] = xs[(tb + j) * 64 + i];
#pragma unroll
        for (int k = 0; k < 5; k++) {
            float wv = ws[o * 321 + i * 5 + k];
#pragma unroll
            for (int t = 0; t < 8; t++) acc[t] = fmaf(xv[t + k], wv, acc[t]);
        }
    }
    const int oc = ocb + o;
    float scl = rsqrtf(bvar[oc] + EPSq) * bg[oc];
    float sh = bnb[oc] - bmean[oc] * scl;
    float cbv = cb[oc];
#pragma unroll
    for (int t = 0; t < 8; t++) {
        float y = (acc[t] + cbv) * scl + sh;
        g_cv[((size_t)b * Tq + t0 + tb + t) * Hq + oc] = y / (1.f + __expf(-y));
    }
}

// ---------------- attention (last query row only) ----------------
__global__ __launch_bounds__(256) void attn_last(
    const float* __restrict__ qkv_w, const float* __restrict__ qkv_b)
{
    __shared__ float q[64];
    __shared__ float sc[Tq];
    __shared__ float red[256];
    __shared__ float vp[256];
    const int bh = blockIdx.x;
    const int b = bh >> 3, h = bh & 7;
    const int tid = threadIdx.x;

    if (tid < 64) {
        int row = h * 64 + tid;
        const float* wr = qkv_w + (size_t)row * Dq;
        const float* ml = g_h2 + ((size_t)b * Tq + (Tq - 1)) * Hq;
        const float* mc = g_cv + ((size_t)b * Tq + (Tq - 1)) * Hq;
        float acc = qkv_b[row];
        for (int k = 0; k < 256; k++) acc = fmaf(ml[k], wr[k], acc);
        for (int k = 0; k < 256; k++) acc = fmaf(mc[k], wr[256 + k], acc);
        q[tid] = acc * 0.125f;
    }
    __syncthreads();

    float lmax = -1e30f;
    for (int t = tid; t < Tq; t += 256) {
        const float4* kp = (const float4*)(g_kv + ((size_t)b * Tq + t) * G4q + h * 64);
        float s = 0.f;
#pragma unroll
        for (int d4 = 0; d4 < 16; d4++) {
            float4 kk = kp[d4];
            float4 qq = ((const float4*)q)[d4];
            s += kk.x * qq.x + kk.y * qq.y + kk.z * qq.z + kk.w * qq.w;
        }
        sc[t] = s;
        lmax = fmaxf(lmax, s);
    }
    red[tid] = lmax; __syncthreads();
    for (int s2 = 128; s2 > 0; s2 >>= 1) {
        if (tid < s2) red[tid] = fmaxf(red[tid], red[tid + s2]);
        __syncthreads();
    }
    float m = red[0];
    __syncthreads();

    float lsum = 0.f;
    for (int t = tid; t < Tq; t += 256) {
        float pe = __expf(sc[t] - m);
        sc[t] = pe;
        lsum += pe;
    }
    red[tid] = lsum; __syncthreads();
    for (int s2 = 128; s2 > 0; s2 >>= 1) {
        if (tid < s2) red[tid] += red[tid + s2];
        __syncthreads();
    }
    float denom = red[0];
    __syncthreads();

    const int d = tid & 63, gg = tid >> 6;
    float acc = 0.f;
    for (int t = gg * 512; t < (gg + 1) * 512; t++)
        acc = fmaf(sc[t], g_kv[((size_t)b * Tq + t) * G4q + 512 + h * 64 + d], acc);
    vp[tid] = acc; __syncthreads();
    if (tid < 64) {
        float o = (vp[tid] + vp[64 + tid] + vp[128 + tid] + vp[192 + tid]) / denom;
        g_at[b * Dq + h * 64 + tid] = o;
    }
}

// ---------------- head ----------------
__global__ __launch_bounds__(512) void head_kernel(
    const float* __restrict__ pw, const float* __restrict__ pb,
    const float* __restrict__ lng, const float* __restrict__ lnb,
    const float* __restrict__ f1w, const float* __restrict__ f1b,
    const float* __restrict__ f2w, const float* __restrict__ f2b,
    float* __restrict__ out)
{
    __shared__ float a[Dq], zn[Dq], z2[Hq], red[512];
    const int b = blockIdx.x, tid = threadIdx.x;
    a[tid] = g_at[b * Dq + tid];
    __syncthreads();

    float acc = pb[tid];
    const float* wr = pw + (size_t)tid * Dq;
    for (int k = 0; k < Dq; k++) acc = fmaf(a[k], wr[k], acc);
    float mrg = (tid < 256) ? g_h2[((size_t)b * Tq + Tq - 1) * Hq + tid]
                            : g_cv[((size_t)b * Tq + Tq - 1) * Hq + tid - 256];
    float z = acc + mrg;

    red[tid] = z; __syncthreads();
    for (int s = 256; s > 0; s >>= 1) {
        if (tid < s) red[tid] += red[tid + s];
        __syncthreads();
    }
    float mu = red[0] / 512.f;
    __syncthreads();
    float dv = z - mu;
    red[tid] = dv * dv; __syncthreads();
    for (int s = 256; s > 0; s >>= 1) {
        if (tid < s) red[tid] += red[tid + s];
        __syncthreads();
    }
    float var = red[0] / 512.f;
    __syncthreads();

    zn[tid] = dv * rsqrtf(var + EPSq) * lng[tid] + lnb[tid];
    __syncthreads();

    if (tid < 256) {
        float a2 = f1b[tid];
        const float* w1 = f1w + (size_t)tid * Dq;
        for (int k = 0; k < Dq; k++) a2 = fmaf(zn[k], w1[k], a2);
        z2[tid] = a2 / (1.f + expf(-a2));
    }
    __syncthreads();

    if (tid < 3) {
        float lg = f2b[tid];
        const float* w2 = f2w + tid * 256;
        for (int j = 0; j < 256; j++) lg = fmaf(z2[j], w2[j], lg);
        if (tid == 0)      out[b]     = tanhf(lg);
        else if (tid == 1) out[4 + b] = (lg > 20.f) ? lg : log1pf(expf(lg));
        else               out[8 + b] = 1.f / (1.f + expf(-lg));
    }
}

// ---------------- launch ----------------
extern "C" void kernel_launch(void* const* d_in, const int* in_sizes, int n_in,
                              void* d_out, int out_size) {
    const float* x     = (const float*)d_in[0];
    const float* wih0  = (const float*)d_in[1];
    const float* whh0  = (const float*)d_in[2];
    const float* bih0  = (const float*)d_in[3];
    const float* bhh0  = (const float*)d_in[4];
    const float* wih1  = (const float*)d_in[5];
    const float* whh1  = (const float*)d_in[6];
    const float* bih1  = (const float*)d_in[7];
    const float* bhh1  = (const float*)d_in[8];
    const float* cw    = (const float*)d_in[9];
    const float* cb    = (const float*)d_in[10];
    const float* bng   = (const float*)d_in[11];
    const float* bnb   = (const float*)d_in[12];
    const float* bnm   = (const float*)d_in[13];
    const float* bnv   = (const float*)d_in[14];
    const float* qkvw  = (const float*)d_in[15];
    const float* qkvb  = (const float*)d_in[16];
    const float* pw    = (const float*)d_in[17];
    const float* pbv   = (const float*)d_in[18];
    const float* lng   = (const float*)d_in[19];
    const float* lnb   = (const float*)d_in[20];
    const float* f1w   = (const float*)d_in[21];
    const float* f1b   = (const float*)d_in[22];
    const float* f2w   = (const float*)d_in[23];
    const float* f2b   = (const float*)d_in[24];
    float* out = (float*)d_out;

    float *gx0, *gx1, *h1, *h2, *cv, *kv;
    cudaGetSymbolAddress((void**)&gx0, g_gx0);
    cudaGetSymbolAddress((void**)&gx1, g_gx1);
    cudaGetSymbolAddress((void**)&h1,  g_h1);
    cudaGetSymbolAddress((void**)&h2,  g_h2);
    cudaGetSymbolAddress((void**)&cv,  g_cv);
    cudaGetSymbolAddress((void**)&kv,  g_kv);

    const int conv_smem = (36 * 64 + 64 * 321) * 4;
    const int mega_smem = (2048 + 1024) * 4;   // 12 KB: gemm tiles / scan state
    cudaFuncSetAttribute(conv_bn_silu, cudaFuncAttributeMaxDynamicSharedMemorySize, conv_smem);

    // 0: reset chunk flags (graph-replay determinism)
    reset_flags<<<1, 192>>>();
    // 1: conv branch (independent of LSTM)
    conv_bn_silu<<<dim3(64, 4, 4), 256, conv_smem>>>(x, cw, cb, bng, bnb, bnm, bnv);
    // 2: fused pipeline: gx0 gemm -> scan0 -> gx1 gemm -> scan1, chunk-overlapped
    mega<<<96, 256, mega_smem>>>(x, wih0, whh0, bih0, bhh0,
                                 wih1, whh1, bih1, bhh1,
                                 gx0, gx1, h1, h2);
    // 3: kv = merged @ qkv_w[512:1536]^T + qkv_b[512:1536]
    gemm128<<<dim3(64, 16), 256>>>(h2, cv, 256, 512, qkvw + 512 * 512, qkvb + 512,
                                   nullptr, kv, G4q);
    // 4: attention (last row only)
    attn_last<<<32, 256>>>(qkvw, qkvb);
    // 5: head
    head_kernel<<<4, 512>>>(pw, pbv, lng, lnb, f1w, f1b, f2w, f2b, out);
}